// round 1
// baseline (speedup 1.0000x reference)
#include <cuda_runtime.h>
#include <cstdint>

// Volume: 256^3 voxels. Inputs (metadata order):
//   d_in[0] vessel_labels  int32  [16777216]
//   d_in[1] id_intensity   float32 [256]
//   d_in[2] id_is_dark     int32  [256]
//   d_in[3] parenchyma     float32 [16777216]
// Output (float32, 67108864 elems): out [16.78M] followed by onehot [3,16.78M]
//   channel 0 = background (!mask), 1 = dark vessel, 2 = bright vessel.

#define N_VOX (256u * 256u * 256u)
#define VEC   (N_VOX / 4u)   // 4,194,304 float4/int4 elements

__global__ __launch_bounds__(256, 8)
void yibei_kernel(const int4* __restrict__ labels4,
                  const float4* __restrict__ par4,
                  const float* __restrict__ id_intensity,
                  const int* __restrict__ id_is_dark,
                  float* __restrict__ out)
{
    // Fused LUT in shared: .x = intensity bits (id 0 forced to 1.0f), .y = dark flag
    __shared__ uint2 s_lut[256];
    {
        int t = threadIdx.x;   // blockDim.x == 256
        float inten = (t == 0) ? 1.0f : __ldg(&id_intensity[t]);
        s_lut[t] = make_uint2(__float_as_uint(inten), (unsigned)__ldg(&id_is_dark[t]));
    }
    __syncthreads();

    unsigned i = blockIdx.x * 256u + threadIdx.x;   // vec4 index; grid exactly covers VEC
    // Streaming loads: labels & parenchyma are read exactly once.
    int4   lab = __ldcs(&labels4[i]);
    float4 p   = __ldcs(&par4[i]);

    float4 o, c0, c1, c2;

    #pragma unroll
    for (int k = 0; k < 4; ++k) {
        int   l  = (&lab.x)[k];
        float pv = (&p.x)[k];
        uint2 e  = s_lut[l];
        float s  = __uint_as_float(e.x);
        bool  m  = (l != 0);
        bool  d  = m & (e.y == 1u);
        (&o.x)[k]  = pv * s;            // lut[0] == 1.0 -> branch-free
        (&c0.x)[k] = m ? 0.0f : 1.0f;
        (&c1.x)[k] = d ? 1.0f : 0.0f;
        (&c2.x)[k] = (m & !d) ? 1.0f : 0.0f;
    }

    float4* o4 = (float4*)out;
    __stcs(&o4[i],               o);
    __stcs(&o4[VEC + i],         c0);   // onehot channel 0 at out + N_VOX
    __stcs(&o4[2u * VEC + i],    c1);
    __stcs(&o4[3u * VEC + i],    c2);
}

extern "C" void kernel_launch(void* const* d_in, const int* in_sizes, int n_in,
                              void* d_out, int out_size)
{
    const int4*   labels4 = (const int4*)d_in[0];
    const float*  id_int  = (const float*)d_in[1];
    const int*    id_dark = (const int*)d_in[2];
    const float4* par4    = (const float4*)d_in[3];
    float*        out     = (float*)d_out;

    dim3 grid(VEC / 256u);   // 16384 blocks
    dim3 block(256);
    yibei_kernel<<<grid, block>>>(labels4, par4, id_int, id_dark, out);
}

// round 2
// speedup vs baseline: 1.0045x; 1.0045x over previous
#include <cuda_runtime.h>
#include <cstdint>

// Volume: 256^3 voxels. Inputs (metadata order):
//   d_in[0] vessel_labels  int32   [16777216]
//   d_in[1] id_intensity   float32 [256]
//   d_in[2] id_is_dark     int32   [256]
//   d_in[3] parenchyma     float32 [16777216]
// Output (float32, 67108864): out [16.78M] then onehot [3,16.78M]
//   ch0 = background, ch1 = dark vessel, ch2 = bright vessel.

#define N_VOX (256u * 256u * 256u)
#define VEC   (N_VOX / 4u)        // 4,194,304 vec4 elements
#define TPB   256u
#define ITEMS 2u                  // vec4 tiles per thread
#define BLOCKS (VEC / (TPB * ITEMS))   // 8192

__global__ __launch_bounds__(TPB, 8)
void yibei_kernel(const int4* __restrict__ labels4,
                  const float4* __restrict__ par4,
                  const float* __restrict__ id_intensity,
                  const int* __restrict__ id_is_dark,
                  float* __restrict__ out)
{
    // Fused LUT in shared: .x = intensity bits (id 0 forced to 1.0f), .y = dark flag
    __shared__ uint2 s_lut[256];
    {
        int t = threadIdx.x;   // blockDim.x == 256
        float inten = (t == 0) ? 1.0f : __ldg(&id_intensity[t]);
        s_lut[t] = make_uint2(__float_as_uint(inten), (unsigned)__ldg(&id_is_dark[t]));
    }
    __syncthreads();

    // Two contiguous-per-warp tiles, TPB apart, so every access stays 128B-coalesced.
    unsigned base = blockIdx.x * (TPB * ITEMS) + threadIdx.x;
    unsigned i0 = base;
    unsigned i1 = base + TPB;

    // Front-batch all global loads (MLP_p1 = 4).
    int4   lab0 = __ldcs(&labels4[i0]);
    int4   lab1 = __ldcs(&labels4[i1]);
    float4 p0   = __ldcs(&par4[i0]);
    float4 p1   = __ldcs(&par4[i1]);

    float4* o4 = (float4*)out;

    #pragma unroll
    for (int t = 0; t < 2; ++t) {
        int4   lab = t ? lab1 : lab0;
        float4 p   = t ? p1   : p0;
        unsigned i = t ? i1   : i0;

        float4 o, c0, c1, c2;
        #pragma unroll
        for (int k = 0; k < 4; ++k) {
            int   l  = (&lab.x)[k];
            float pv = (&p.x)[k];
            uint2 e  = s_lut[l];
            bool  m  = (l != 0);
            bool  d  = m & (e.y == 1u);
            (&o.x)[k]  = pv * __uint_as_float(e.x);   // lut[0] == 1.0 -> branch-free
            (&c0.x)[k] = m ? 0.0f : 1.0f;
            (&c1.x)[k] = d ? 1.0f : 0.0f;
            (&c2.x)[k] = (m & !d) ? 1.0f : 0.0f;
        }

        __stcs(&o4[i],            o);
        __stcs(&o4[VEC + i],      c0);
        __stcs(&o4[2u * VEC + i], c1);
        __stcs(&o4[3u * VEC + i], c2);
    }
}

extern "C" void kernel_launch(void* const* d_in, const int* in_sizes, int n_in,
                              void* d_out, int out_size)
{
    const int4*   labels4 = (const int4*)d_in[0];
    const float*  id_int  = (const float*)d_in[1];
    const int*    id_dark = (const int*)d_in[2];
    const float4* par4    = (const float4*)d_in[3];
    float*        out     = (float*)d_out;

    yibei_kernel<<<BLOCKS, TPB>>>(labels4, par4, id_int, id_dark, out);
}